// round 3
// baseline (speedup 1.0000x reference)
#include <cuda_runtime.h>
#include <math.h>
#include <math_constants.h>
#include <stdint.h>

// Bahdanau attention, B=32, T=4096, QD=VD=AD=256, fp32 in/out.
// out = [ c (32*256) | a (32*4096) ]
//
//   K1 qproj:    qb[b][a] = Wq[a,:]·query[b,:] + bq[a] + bv[a];  c <- 0
//   K2 score:    e[b][t]  = sum_a wv_score[a] * tanh(qb[b][a] + values[b,t,:]·Wv[a,:])
//                tf32 mma.sync GEMM fused with tanh + wv reduce.
//                (bv_score dropped: softmax shift-invariant, e not an output)
//   K3 softmax:  a[b][:] = softmax(e[b][:])   (in place in out)
//   K4 context:  c[b][v] = sum_t a[b][t] * values[b][t][v]

#define B_  32
#define T_  4096
#define D_  256

#define TM   64          // M rows per block
#define TK   32          // K chunk
#define VS_S 36          // smem stride (floats): bank = (4*row + k) % 32, conflict-free frags

__device__ float g_qb[B_ * D_];

__device__ __forceinline__ uint32_t f2tf32(float x) {
    uint32_t u;
    asm("cvt.rna.tf32.f32 %0, %1;" : "=r"(u) : "f"(x));
    return u;
}

__device__ __forceinline__ void mma_tf32(float& d0, float& d1, float& d2, float& d3,
                                         uint32_t a0, uint32_t a1, uint32_t a2, uint32_t a3,
                                         uint32_t b0, uint32_t b1) {
    asm("mma.sync.aligned.m16n8k8.row.col.f32.tf32.tf32.f32 "
        "{%0,%1,%2,%3}, {%4,%5,%6,%7}, {%8,%9}, {%0,%1,%2,%3};"
        : "+f"(d0), "+f"(d1), "+f"(d2), "+f"(d3)
        : "r"(a0), "r"(a1), "r"(a2), "r"(a3), "r"(b0), "r"(b1));
}

// ---------------------------------------------------------------- K1: qproj
__global__ void qproj_kernel(const float* __restrict__ query,
                             const float* __restrict__ Wq,
                             const float* __restrict__ bq,
                             const float* __restrict__ bv,
                             float* __restrict__ out_c)
{
    __shared__ float qs[D_];
    int b = blockIdx.x;
    int a = threadIdx.x;
    qs[a] = query[b * D_ + a];
    __syncthreads();
    float acc = bq[a] + bv[a];
    const float* wrow = Wq + (size_t)a * D_;
#pragma unroll 8
    for (int q = 0; q < D_; q++) acc += wrow[q] * qs[q];
    g_qb[b * D_ + a] = acc;
    out_c[b * D_ + a] = 0.0f;   // zero context accumulator (atomicAdd target)
}

// ---------------------------------------------------------------- K2: score (tf32 mma)
// Block: 256 thr = 8 warps. Tile M=64 x N=256, K-chunks of 32.
// Warp w owns N-slice [w*32, w*32+32) for all 64 rows:
//   4 m-tiles (m16) x 4 n-tiles (n8) of m16n8k8 accum frags = 64 fp32 regs/thread.
__global__ __launch_bounds__(256) void score_kernel(
    const float* __restrict__ values,
    const float* __restrict__ Wv,
    const float* __restrict__ wv_score,
    float* __restrict__ e_out)
{
    __shared__ uint32_t Vs[TM][VS_S];    // values tile, tf32 bits (aliased by partials later)
    __shared__ uint32_t Ws[D_][VS_S];    // Wv tile, tf32 bits
    __shared__ float qb_s[D_];
    __shared__ float wv_s[D_];

    const int tid = threadIdx.x;
    const int tx  = tid & 31;
    const int w   = tid >> 5;
    const int g   = tx >> 2;      // groupID
    const int tg  = tx & 3;       // thread-in-group
    const int row0 = blockIdx.x * TM;     // global row = b*T + t
    const int b = row0 >> 12;             // TM divides T -> single b per block

    qb_s[tid] = g_qb[b * D_ + tid];
    wv_s[tid] = wv_score[tid];

    float acc[4][4][4];
#pragma unroll
    for (int mt = 0; mt < 4; mt++)
#pragma unroll
        for (int nt = 0; nt < 4; nt++)
#pragma unroll
            for (int r = 0; r < 4; r++) acc[mt][nt][r] = 0.0f;

    for (int k0 = 0; k0 < D_; k0 += TK) {
        // Values tile: 64x32, coalesced; convert fp32 -> tf32 once at store.
#pragma unroll
        for (int l = 0; l < (TM * TK) / 256; l++) {
            int idx = tid + l * 256;
            int i = idx >> 5, kk = idx & 31;
            Vs[i][kk] = f2tf32(values[(size_t)(row0 + i) * D_ + k0 + kk]);
        }
        // Wv tile: 256x32, coalesced.
#pragma unroll
        for (int l = 0; l < (D_ * TK) / 256; l++) {
            int idx = tid + l * 256;
            int aa = idx >> 5, kk = idx & 31;
            Ws[aa][kk] = f2tf32(Wv[(size_t)aa * D_ + k0 + kk]);
        }
        __syncthreads();

#pragma unroll
        for (int kk = 0; kk < TK; kk += 8) {
            // A fragments: rows mt*16 + g (+8), cols kk + tg (+4)
            uint32_t af[4][4];
#pragma unroll
            for (int mt = 0; mt < 4; mt++) {
                af[mt][0] = Vs[mt * 16 + g    ][kk + tg    ];
                af[mt][1] = Vs[mt * 16 + g + 8][kk + tg    ];
                af[mt][2] = Vs[mt * 16 + g    ][kk + tg + 4];
                af[mt][3] = Vs[mt * 16 + g + 8][kk + tg + 4];
            }
            // B fragments: B[k][n] = Wv[n][k]; n = w*32 + nt*8 + g
            uint32_t bf[4][2];
#pragma unroll
            for (int nt = 0; nt < 4; nt++) {
                int a = w * 32 + nt * 8 + g;
                bf[nt][0] = Ws[a][kk + tg    ];
                bf[nt][1] = Ws[a][kk + tg + 4];
            }
#pragma unroll
            for (int mt = 0; mt < 4; mt++)
#pragma unroll
                for (int nt = 0; nt < 4; nt++)
                    mma_tf32(acc[mt][nt][0], acc[mt][nt][1], acc[mt][nt][2], acc[mt][nt][3],
                             af[mt][0], af[mt][1], af[mt][2], af[mt][3],
                             bf[nt][0], bf[nt][1]);
        }
        __syncthreads();
    }

    // Epilogue: p[row] = sum over warp's 32 cols of wv[a]*tanh(qb[a] + acc).
    // C-frag: c0 (row g,   col n0+2tg), c1 (row g,   col n0+2tg+1),
    //         c2 (row g+8, col n0+2tg), c3 (row g+8, col n0+2tg+1)
    float* part = (float*)&Vs[0][0];     // [64][8], aliases dead Vs (synced above)

#pragma unroll
    for (int mt = 0; mt < 4; mt++) {
        float slo = 0.0f, shi = 0.0f;
#pragma unroll
        for (int nt = 0; nt < 4; nt++) {
            int c = w * 32 + nt * 8 + tg * 2;
            slo += wv_s[c    ] * tanhf(qb_s[c    ] + acc[mt][nt][0]);
            slo += wv_s[c + 1] * tanhf(qb_s[c + 1] + acc[mt][nt][1]);
            shi += wv_s[c    ] * tanhf(qb_s[c    ] + acc[mt][nt][2]);
            shi += wv_s[c + 1] * tanhf(qb_s[c + 1] + acc[mt][nt][3]);
        }
        // reduce across the 4-lane group (tg)
        slo += __shfl_xor_sync(0xffffffffu, slo, 1);
        slo += __shfl_xor_sync(0xffffffffu, slo, 2);
        shi += __shfl_xor_sync(0xffffffffu, shi, 1);
        shi += __shfl_xor_sync(0xffffffffu, shi, 2);
        if (tg == 0) {
            part[(mt * 16 + g    ) * 8 + w] = slo;
            part[(mt * 16 + g + 8) * 8 + w] = shi;
        }
    }
    __syncthreads();

    // Cross-warp reduce: 64 rows x 8 warp-partials.
    if (tid < TM) {
        float s = 0.0f;
#pragma unroll
        for (int j = 0; j < 8; j++) s += part[tid * 8 + j];
        e_out[row0 + tid] = s;
    }
}

// ---------------------------------------------------------------- K3: softmax
// Shift-normalized: __expf's ~1ulp error cancels in the ratio.
__global__ void softmax_kernel(float* __restrict__ a)
{
    __shared__ float red[256];
    const int b = blockIdx.x;
    const int tid = threadIdx.x;
    float* row = a + (size_t)b * T_;

    float v[T_ / 256];
    float mx = -CUDART_INF_F;
#pragma unroll
    for (int i = 0; i < T_ / 256; i++) {
        v[i] = row[tid + i * 256];
        mx = fmaxf(mx, v[i]);
    }
    red[tid] = mx;
    __syncthreads();
    for (int s = 128; s > 0; s >>= 1) {
        if (tid < s) red[tid] = fmaxf(red[tid], red[tid + s]);
        __syncthreads();
    }
    mx = red[0];
    __syncthreads();

    float sum = 0.0f;
#pragma unroll
    for (int i = 0; i < T_ / 256; i++) {
        v[i] = __expf(v[i] - mx);
        sum += v[i];
    }
    red[tid] = sum;
    __syncthreads();
    for (int s = 128; s > 0; s >>= 1) {
        if (tid < s) red[tid] += red[tid + s];
        __syncthreads();
    }
    float inv = 1.0f / red[0];
#pragma unroll
    for (int i = 0; i < T_ / 256; i++) row[tid + i * 256] = v[i] * inv;
}

// ---------------------------------------------------------------- K4: context
__global__ void context_kernel(const float* __restrict__ values,
                               const float* __restrict__ a,
                               float* __restrict__ c)
{
    __shared__ float as[128];
    const int b  = blockIdx.x;
    const int tc = blockIdx.y;       // 32 chunks of 128 t
    const int tid = threadIdx.x;     // v column

    if (tid < 128) as[tid] = a[(size_t)b * T_ + tc * 128 + tid];
    __syncthreads();

    const float* vp = values + ((size_t)b * T_ + (size_t)tc * 128) * D_ + tid;
    float acc = 0.0f;
#pragma unroll 4
    for (int t = 0; t < 128; t++) acc += as[t] * vp[(size_t)t * D_];
    atomicAdd(&c[b * D_ + tid], acc);
}

// ---------------------------------------------------------------- launch
extern "C" void kernel_launch(void* const* d_in, const int* in_sizes, int n_in,
                              void* d_out, int out_size)
{
    const float* query    = (const float*)d_in[0];
    const float* values   = (const float*)d_in[1];
    const float* Wq       = (const float*)d_in[2];
    const float* bq       = (const float*)d_in[3];
    const float* Wv       = (const float*)d_in[4];
    const float* bv       = (const float*)d_in[5];
    const float* wv_score = (const float*)d_in[6];
    // d_in[7] = bv_score: softmax shift-invariant, intentionally unused.

    float* out = (float*)d_out;
    float* c = out;                  // [32, 256]
    float* a = out + B_ * D_;        // [32, 4096]

    qproj_kernel<<<B_, D_>>>(query, Wq, bq, bv, c);
    score_kernel<<<(B_ * T_) / TM, 256>>>(values, Wv, wv_score, a);
    softmax_kernel<<<B_, 256>>>(a);
    context_kernel<<<dim3(B_, T_ / 128), D_>>>(values, a, c);
}

// round 6
// speedup vs baseline: 1.2097x; 1.2097x over previous
#include <cuda_runtime.h>
#include <math.h>
#include <math_constants.h>
#include <stdint.h>

// Bahdanau attention, B=32, T=4096, QD=VD=AD=256, fp32 in/out.
// out = [ c (32*256) | a (32*4096) ]
//
//   K1 qproj:    qb[b][a] = Wq[a,:]·query[b,:] + bq[a] + bv[a];  c <- 0
//   K2 score:    e[b][t]  = sum_a wv_score[a] * tanh(qb[b][a] + values[b,t,:]·Wv[a,:])
//                tf32 mma.sync GEMM, cp.async 2-stage pipeline, fused tanh + wv reduce.
//                Raw fp32 staged in smem; tf32 mma truncates mantissa (HW semantics).
//   K3 softmax:  a[b][:] = softmax(e[b][:])   (in place)
//   K4 context:  c[b][v] = sum_t a[b][t] * values[b][t][v]   (float4 / LDG.128)

#define B_  32
#define T_  4096
#define D_  256

#define TM   64
#define TK   32
#define SST  36        // smem row stride (floats); 144B, 16B-aligned, conflict-free frags

// dynamic smem layout (floats)
#define OFF_VS0 0
#define OFF_WS0 (TM * SST)                    // 2304
#define OFF_VS1 (OFF_WS0 + D_ * SST)          // 11520
#define OFF_WS1 (OFF_VS1 + TM * SST)          // 13824
#define OFF_QB  (OFF_WS1 + D_ * SST)          // 23040
#define OFF_WV  (OFF_QB + D_)                 // 23296
#define SMEM_FLOATS (OFF_WV + D_)             // 23552
#define SMEM_BYTES  (SMEM_FLOATS * 4)         // 94208

__device__ float g_qb[B_ * D_];

__device__ __forceinline__ uint32_t smem_u32(const void* p) {
    return (uint32_t)__cvta_generic_to_shared(p);
}
__device__ __forceinline__ void cp16(void* dst_smem, const void* src) {
    asm volatile("cp.async.cg.shared.global [%0], [%1], 16;\n"
                 :: "r"(smem_u32(dst_smem)), "l"(src));
}
__device__ __forceinline__ void cp_commit() {
    asm volatile("cp.async.commit_group;\n");
}
template <int N>
__device__ __forceinline__ void cp_wait() {
    asm volatile("cp.async.wait_group %0;\n" :: "n"(N));
}

__device__ __forceinline__ void mma_tf32(float& d0, float& d1, float& d2, float& d3,
                                         uint32_t a0, uint32_t a1, uint32_t a2, uint32_t a3,
                                         uint32_t b0, uint32_t b1) {
    asm("mma.sync.aligned.m16n8k8.row.col.f32.tf32.tf32.f32 "
        "{%0,%1,%2,%3}, {%4,%5,%6,%7}, {%8,%9}, {%0,%1,%2,%3};"
        : "+f"(d0), "+f"(d1), "+f"(d2), "+f"(d3)
        : "r"(a0), "r"(a1), "r"(a2), "r"(a3), "r"(b0), "r"(b1));
}

// ---------------------------------------------------------------- K1: qproj
__global__ void qproj_kernel(const float* __restrict__ query,
                             const float* __restrict__ Wq,
                             const float* __restrict__ bq,
                             const float* __restrict__ bv,
                             float* __restrict__ out_c)
{
    __shared__ float qs[D_];
    int b = blockIdx.x;
    int a = threadIdx.x;
    qs[a] = query[b * D_ + a];
    __syncthreads();
    float acc = bq[a] + bv[a];
    const float* wrow = Wq + (size_t)a * D_;
#pragma unroll 8
    for (int q = 0; q < D_; q++) acc += wrow[q] * qs[q];
    g_qb[b * D_ + a] = acc;
    out_c[b * D_ + a] = 0.0f;   // zero context accumulator (atomicAdd target)
}

// ---------------------------------------------------------------- K2: score
// 256 thr = 8 warps. Tile M=64 x N=256, K-chunk 32, 2-stage cp.async double buffer.
// Warp w owns N-slice [w*32, w*32+32): 4 m-tiles x 4 n-tiles m16n8k8 = 64 accum regs.
__device__ __forceinline__ void load_chunk(const float* __restrict__ gV,
                                           const float* __restrict__ gW,
                                           float* sV, float* sW, int tid)
{
    // Vs: 64x32 = 512 float4, 2 per thread
#pragma unroll
    for (int l = 0; l < 2; l++) {
        int idx = tid + 256 * l;
        int i = idx >> 3, j = idx & 7;
        cp16(sV + i * SST + j * 4, gV + (size_t)i * D_ + j * 4);
    }
    // Ws: 256x32 = 2048 float4, 8 per thread
#pragma unroll
    for (int l = 0; l < 8; l++) {
        int idx = tid + 256 * l;
        int aa = idx >> 3, j = idx & 7;
        cp16(sW + aa * SST + j * 4, gW + (size_t)aa * D_ + j * 4);
    }
}

__global__ __launch_bounds__(256) void score_kernel(
    const float* __restrict__ values,
    const float* __restrict__ Wv,
    const float* __restrict__ wv_score,
    float* __restrict__ e_out)
{
    extern __shared__ float smem[];
    float* Vbuf[2] = { smem + OFF_VS0, smem + OFF_VS1 };
    float* Wbuf[2] = { smem + OFF_WS0, smem + OFF_WS1 };
    float* qb_s = smem + OFF_QB;
    float* wv_s = smem + OFF_WV;

    const int tid = threadIdx.x;
    const int tx  = tid & 31;
    const int w   = tid >> 5;
    const int g   = tx >> 2;      // groupID
    const int tg  = tx & 3;       // thread-in-group
    const int row0 = blockIdx.x * TM;     // global row = b*T + t
    const int b = row0 >> 12;

    const float* gV = values + (size_t)row0 * D_;

    // prologue: stage chunks 0 and 1
    load_chunk(gV + 0 * TK, Wv + 0 * TK, Vbuf[0], Wbuf[0], tid);
    cp_commit();
    load_chunk(gV + 1 * TK, Wv + 1 * TK, Vbuf[1], Wbuf[1], tid);
    cp_commit();

    qb_s[tid] = g_qb[b * D_ + tid];
    wv_s[tid] = wv_score[tid];

    float acc[4][4][4];
#pragma unroll
    for (int mt = 0; mt < 4; mt++)
#pragma unroll
        for (int nt = 0; nt < 4; nt++)
#pragma unroll
            for (int r = 0; r < 4; r++) acc[mt][nt][r] = 0.0f;

#pragma unroll
    for (int ic = 0; ic < D_ / TK; ic++) {
        cp_wait<1>();                 // chunk ic resident
        __syncthreads();

        const float* Vs = Vbuf[ic & 1];
        const float* Ws = Wbuf[ic & 1];

#pragma unroll
        for (int kk = 0; kk < TK; kk += 8) {
            uint32_t af[4][4];
#pragma unroll
            for (int mt = 0; mt < 4; mt++) {
                af[mt][0] = __float_as_uint(Vs[(mt * 16 + g    ) * SST + kk + tg    ]);
                af[mt][1] = __float_as_uint(Vs[(mt * 16 + g + 8) * SST + kk + tg    ]);
                af[mt][2] = __float_as_uint(Vs[(mt * 16 + g    ) * SST + kk + tg + 4]);
                af[mt][3] = __float_as_uint(Vs[(mt * 16 + g + 8) * SST + kk + tg + 4]);
            }
            uint32_t bf[4][2];
#pragma unroll
            for (int nt = 0; nt < 4; nt++) {
                int a = w * 32 + nt * 8 + g;
                bf[nt][0] = __float_as_uint(Ws[a * SST + kk + tg    ]);
                bf[nt][1] = __float_as_uint(Ws[a * SST + kk + tg + 4]);
            }
#pragma unroll
            for (int mt = 0; mt < 4; mt++)
#pragma unroll
                for (int nt = 0; nt < 4; nt++)
                    mma_tf32(acc[mt][nt][0], acc[mt][nt][1], acc[mt][nt][2], acc[mt][nt][3],
                             af[mt][0], af[mt][1], af[mt][2], af[mt][3],
                             bf[nt][0], bf[nt][1]);
        }
        __syncthreads();              // all warps done with buf[ic&1]
        if (ic + 2 < D_ / TK)
            load_chunk(gV + (ic + 2) * TK, Wv + (ic + 2) * TK,
                       Vbuf[ic & 1], Wbuf[ic & 1], tid);
        cp_commit();                  // one group per iter keeps wait<1> counting exact
    }

    // Epilogue: p[row] = sum over warp's 32 cols of wv[a]*tanh(qb[a] + acc).
    float* part = Vbuf[0];            // [64][8] partials, aliases dead V buffer

#pragma unroll
    for (int mt = 0; mt < 4; mt++) {
        float slo = 0.0f, shi = 0.0f;
#pragma unroll
        for (int nt = 0; nt < 4; nt++) {
            int c = w * 32 + nt * 8 + tg * 2;
            slo += wv_s[c    ] * tanhf(qb_s[c    ] + acc[mt][nt][0]);
            slo += wv_s[c + 1] * tanhf(qb_s[c + 1] + acc[mt][nt][1]);
            shi += wv_s[c    ] * tanhf(qb_s[c    ] + acc[mt][nt][2]);
            shi += wv_s[c + 1] * tanhf(qb_s[c + 1] + acc[mt][nt][3]);
        }
        slo += __shfl_xor_sync(0xffffffffu, slo, 1);
        slo += __shfl_xor_sync(0xffffffffu, slo, 2);
        shi += __shfl_xor_sync(0xffffffffu, shi, 1);
        shi += __shfl_xor_sync(0xffffffffu, shi, 2);
        if (tg == 0) {
            part[(mt * 16 + g    ) * 8 + w] = slo;
            part[(mt * 16 + g + 8) * 8 + w] = shi;
        }
    }
    __syncthreads();

    if (tid < TM) {
        float s = 0.0f;
#pragma unroll
        for (int j = 0; j < 8; j++) s += part[tid * 8 + j];
        e_out[row0 + tid] = s;
    }
}

// ---------------------------------------------------------------- K3: softmax
__global__ void softmax_kernel(float* __restrict__ a)
{
    __shared__ float red[256];
    const int b = blockIdx.x;
    const int tid = threadIdx.x;
    float* row = a + (size_t)b * T_;

    float v[T_ / 256];
    float mx = -CUDART_INF_F;
#pragma unroll
    for (int i = 0; i < T_ / 256; i++) {
        v[i] = row[tid + i * 256];
        mx = fmaxf(mx, v[i]);
    }
    red[tid] = mx;
    __syncthreads();
    for (int s = 128; s > 0; s >>= 1) {
        if (tid < s) red[tid] = fmaxf(red[tid], red[tid + s]);
        __syncthreads();
    }
    mx = red[0];
    __syncthreads();

    float sum = 0.0f;
#pragma unroll
    for (int i = 0; i < T_ / 256; i++) {
        v[i] = __expf(v[i] - mx);
        sum += v[i];
    }
    red[tid] = sum;
    __syncthreads();
    for (int s = 128; s > 0; s >>= 1) {
        if (tid < s) red[tid] += red[tid + s];
        __syncthreads();
    }
    float inv = 1.0f / red[0];
#pragma unroll
    for (int i = 0; i < T_ / 256; i++) row[tid + i * 256] = v[i] * inv;
}

// ---------------------------------------------------------------- K4: context
// float4 loads: block = 256 thr, grid (B, T/256). Lane group covers 256 v-cols
// as 64 float4; 4 t-subgroups of 64 rows each. LDG.128, MLP via unroll.
__global__ void context_kernel(const float* __restrict__ values,
                               const float* __restrict__ a,
                               float* __restrict__ c)
{
    __shared__ float as[256];
    const int b   = blockIdx.x;
    const int tc  = blockIdx.y;          // T/256 chunks
    const int tid = threadIdx.x;
    const int c4  = tid & 63;            // float4 column index
    const int tg  = tid >> 6;            // t subgroup 0..3 (64 rows each)

    as[tid] = a[(size_t)b * T_ + tc * 256 + tid];
    __syncthreads();

    const float4* vp = (const float4*)(values + ((size_t)b * T_ + tc * 256 + tg * 64) * D_) + c4;
    const float* aw = as + tg * 64;

    float4 acc = make_float4(0.f, 0.f, 0.f, 0.f);
#pragma unroll 8
    for (int t = 0; t < 64; t++) {
        float4 v = vp[(size_t)t * (D_ / 4)];
        float wgt = aw[t];
        acc.x += wgt * v.x; acc.y += wgt * v.y;
        acc.z += wgt * v.z; acc.w += wgt * v.w;
    }
    float* cp = c + b * D_ + c4 * 4;
    atomicAdd(cp + 0, acc.x);
    atomicAdd(cp + 1, acc.y);
    atomicAdd(cp + 2, acc.z);
    atomicAdd(cp + 3, acc.w);
}

// ---------------------------------------------------------------- launch
extern "C" void kernel_launch(void* const* d_in, const int* in_sizes, int n_in,
                              void* d_out, int out_size)
{
    const float* query    = (const float*)d_in[0];
    const float* values   = (const float*)d_in[1];
    const float* Wq       = (const float*)d_in[2];
    const float* bq       = (const float*)d_in[3];
    const float* Wv       = (const float*)d_in[4];
    const float* bv       = (const float*)d_in[5];
    const float* wv_score = (const float*)d_in[6];
    // d_in[7] = bv_score: softmax shift-invariant, intentionally unused.

    float* out = (float*)d_out;
    float* c = out;                  // [32, 256]
    float* a = out + B_ * D_;        // [32, 4096]

    cudaFuncSetAttribute(score_kernel,
                         cudaFuncAttributeMaxDynamicSharedMemorySize, SMEM_BYTES);

    qproj_kernel<<<B_, D_>>>(query, Wq, bq, bv, c);
    score_kernel<<<(B_ * T_) / TM, 256, SMEM_BYTES>>>(values, Wv, wv_score, a);
    softmax_kernel<<<B_, 256>>>(a);
    context_kernel<<<dim3(B_, T_ / 256), 256>>>(values, a, c);
}